// round 13
// baseline (speedup 1.0000x reference)
#include <cuda_runtime.h>
#include <math.h>

constexpr int NDIM  = 80;
constexpr int BATCH = 64;
constexpr int SEQ   = 1000;
constexpr int KST   = 12;
constexpr int NBK   = BATCH * KST;   // 768
constexpr int TS    = 64;            // samples per tile (kernel B)
constexpr int NT    = 8;             // tiles per block
constexpr int CHUNK = 512;           // samples per block chunk
constexpr int MSP   = 84;            // msh row stride (floats)
constexpr int DSP   = 84;            // ds sample-row stride (floats)
constexpr int RSP   = 68;            // red row stride
constexpr int AST   = 84;            // chol A row stride

constexpr float LOG_2PI = 1.837877066409345339082f;
constexpr float EPS = 1e-5f;

__device__ float g_minv[(size_t)NBK * NDIM * NDIM];   // row-major L^-1 (dense, zeros above diag)
__device__ float g_logdet[NBK];
__device__ float g_negc[(size_t)NBK * NDIM];          // -L^-1*mu per (b,k)

typedef unsigned long long ull;
__device__ __forceinline__ ull fma2(ull a, ull b, ull c) {
    ull d; asm("fma.rn.f32x2 %0,%1,%2,%3;" : "=l"(d) : "l"(a), "l"(b), "l"(c)); return d;
}
__device__ __forceinline__ ull mul2(ull a, ull b) {
    ull d; asm("mul.rn.f32x2 %0,%1,%2;" : "=l"(d) : "l"(a), "l"(b)); return d;
}
__device__ __forceinline__ ull dup2(float x) {
    ull d; asm("mov.b64 %0,{%1,%1};" : "=l"(d) : "f"(x)); return d;
}
__device__ __forceinline__ float2 asf2(ull v) {
    float2 r; asm("mov.b64 {%0,%1},%2;" : "=f"(r.x), "=f"(r.y) : "l"(v)); return r;
}
__device__ __forceinline__ void cpa16(float* dst, const float* src, int nbytes) {
    unsigned int d = (unsigned int)__cvta_generic_to_shared(dst);
    asm volatile("cp.async.cg.shared.global [%0], [%1], 16, %2;"
                 :: "r"(d), "l"(src), "r"(nbytes));
}
__device__ __forceinline__ void cpa_commit() { asm volatile("cp.async.commit_group;"); }
__device__ __forceinline__ void cpa_wait0()  { asm volatile("cp.async.wait_group 0;" ::: "memory"); }

// ---------------------------------------------------------------------------
// Kernel A (R9 structure): elimination (LDS.128 rank-1 updates), scale to L,
// logdet, sync-free triangular inverse into upper triangle, negc; store
// ROW-MAJOR dense inverse. 96 threads, thread i = row i.
// ---------------------------------------------------------------------------
__global__ __launch_bounds__(96) void chol_inv_kernel(const float* __restrict__ sigma,
                                                      const float* __restrict__ mu) {
    __shared__ __align__(16) float A[NDIM * AST];      // 26.9 KB
    __shared__ __align__(16) float colbuf[NDIM + 4];
    __shared__ __align__(16) float rinv[NDIM];
    __shared__ float lbuf[NDIM];
    __shared__ float mush[NDIM];
    __shared__ float dinvsh;

    const int bk  = blockIdx.x;
    const int tid = threadIdx.x;
    const int i   = tid;
    const float* Sg = sigma + (size_t)bk * NDIM * NDIM;

    for (int idx = tid; idx < NDIM * NDIM; idx += 96) {
        int r = idx / NDIM, c = idx % NDIM;
        float v = Sg[idx];
        if (r == c) v += EPS;
        A[r * AST + c] = v;
    }
    __syncthreads();

    for (int k = 0; k < NDIM - 1; ++k) {
        if (tid < NDIM) colbuf[tid] = A[tid * AST + k];
        if (tid == 0) dinvsh = 1.0f / A[k * AST + k];
        __syncthreads();
        if (i > k && i < NDIM) {
            float nci = -colbuf[i] * dinvsh;
            ull  nc2 = dup2(nci);
            float* Ai = A + i * AST;
            int j = k + 1;
            for (; j <= i && (j & 3); ++j) Ai[j] = fmaf(nci, colbuf[j], Ai[j]);
            #pragma unroll 2
            for (; j + 3 <= i; j += 4) {
                ulonglong2 a2 = *reinterpret_cast<ulonglong2*>(Ai + j);
                ulonglong2 c2 = *reinterpret_cast<const ulonglong2*>(colbuf + j);
                a2.x = fma2(nc2, c2.x, a2.x);
                a2.y = fma2(nc2, c2.y, a2.y);
                *reinterpret_cast<ulonglong2*>(Ai + j) = a2;
            }
            for (; j <= i; ++j) Ai[j] = fmaf(nci, colbuf[j], Ai[j]);
        }
        __syncthreads();
    }

    if (tid < NDIM) {
        float d = A[tid * AST + tid];
        rinv[tid] = 1.0f / sqrtf(d);
        lbuf[tid] = logf(d);
    }
    if (tid < NDIM) mush[tid] = mu[(size_t)bk * NDIM + tid];
    __syncthreads();
    if (tid == 0) {
        float s = 0.0f;
        for (int j = 0; j < NDIM; ++j) s += lbuf[j];
        g_logdet[bk] = 0.5f * s;
    }
    if (i < NDIM) {
        float* Ai = A + i * AST;
        int k = 0;
        #pragma unroll 2
        for (; k + 3 <= i - 1; k += 4) {
            ulonglong2 a2 = *reinterpret_cast<ulonglong2*>(Ai + k);
            ulonglong2 r2 = *reinterpret_cast<const ulonglong2*>(rinv + k);
            a2.x = mul2(a2.x, r2.x);
            a2.y = mul2(a2.y, r2.y);
            *reinterpret_cast<ulonglong2*>(Ai + k) = a2;
        }
        for (; k <= i - 1; ++k) Ai[k] *= rinv[k];
    }
    __syncthreads();

    // X = L^-1 into the UPPER triangle (X[i][jj] stored at A[jj][i])
    if (i > 0 && i < NDIM) {
        for (int jj = i - 1; jj >= 0; --jj) {
            float s0 = rinv[i] * A[i * AST + jj];
            float s1 = 0.f, s2 = 0.f, s3 = 0.f;
            int k = jj + 1;
            for (; k + 3 < i; k += 4) {
                s0 = fmaf(A[k * AST + i],     A[k * AST + jj],     s0);
                s1 = fmaf(A[(k+1) * AST + i], A[(k+1) * AST + jj], s1);
                s2 = fmaf(A[(k+2) * AST + i], A[(k+2) * AST + jj], s2);
                s3 = fmaf(A[(k+3) * AST + i], A[(k+3) * AST + jj], s3);
            }
            for (; k < i; ++k)
                s0 = fmaf(A[k * AST + i], A[k * AST + jj], s0);
            A[jj * AST + i] = -rinv[jj] * ((s0 + s1) + (s2 + s3));
        }
    }
    __syncthreads();

    if (i < NDIM) {
        float s = rinv[i] * mush[i];
        for (int jj = 0; jj < i; ++jj)
            s = fmaf(A[jj * AST + i], mush[jj], s);
        g_negc[(size_t)bk * NDIM + i] = -s;
    }

    // Store ROW-MAJOR dense inverse: out[i][j] = X[i][j]
    float* out = g_minv + (size_t)bk * NDIM * NDIM;
    for (int idx = tid; idx < NDIM * NDIM; idx += 96) {
        int r = idx / NDIM, c = idx % NDIM;   // out[r][c] = X[r][c]
        float v;
        if (c < r)       v = A[c * AST + r];  // X[r][c] at A[c][r]
        else if (c == r) v = rinv[r];
        else             v = 0.0f;
        out[idx] = v;
    }
}

// ---------------------------------------------------------------------------
// Kernel B: block = (s-chunk of 512, k, b); 8 tiles of 64 samples.
// msh (Minv row-major) + negc staged ONCE via cp.async; ds (x direct copy,
// [s][j] rows, stride 84) double-buffered with cp.async prefetch of tile t+1
// during tile t's mainloop. j-PAIRED f32x2 accumulators: both operands are
// contiguous pairs -> zero dup MOVs.
// Warp g: rows {4g..4g+3} U {76-4g..79-4g}; lane: rsub = tx>>4 picks 2+2 rows,
// sg = tx&15 picks samples {sg, sg+16, sg+32, sg+48}. 336 fma2/lane/tile.
// ---------------------------------------------------------------------------
__global__ __launch_bounds__(320, 2) void ll_kernel(const float* __restrict__ x,
                                                    float* __restrict__ out) {
    extern __shared__ __align__(16) float sm[];
    float* msh  = sm;                          // [80][84]
    float* ds0  = sm + NDIM * MSP;             // [64][84]
    float* ds1  = ds0 + TS * DSP;              // [64][84]
    float* red  = ds1 + TS * DSP;              // [10][68]
    float* ncsh = red + 10 * RSP;              // [80]

    const int tid = threadIdx.x;
    const int tx  = tid & 31;
    const int ty  = tid >> 5;                  // warp 0..9
    const int sc  = blockIdx.x;                // s-chunk 0/1
    const int k   = blockIdx.y;
    const int b   = blockIdx.z;
    const int bk  = b * KST + k;
    const int cs0 = sc * CHUNK;

    // ---- Prologue: cp.async stage msh + ncsh + ds0 (tile 0) ----
    const float* mv = g_minv + (size_t)bk * NDIM * NDIM;
    #pragma unroll
    for (int u = 0; u < 5; ++u) {
        int q = tid + u * 320;                 // 0..1599
        int i2 = q / 20, j4 = q % 20;
        cpa16(msh + i2 * MSP + 4 * j4, mv + 4 * q, 16);
    }
    if (tid < 20) cpa16(ncsh + 4 * tid, g_negc + (size_t)bk * NDIM + 4 * tid, 16);
    {
        const float* xt = x + ((size_t)b * SEQ + cs0) * NDIM;
        #pragma unroll
        for (int u = 0; u < 4; ++u) {
            int q = tid + u * 320;             // 0..1279
            int s = q / 20, j4 = q % 20;
            cpa16(ds0 + s * DSP + 4 * j4, xt + s * NDIM + 4 * j4, 16);  // first tile always full
        }
    }
    cpa_commit();
    cpa_wait0();
    __syncthreads();

    const int g    = ty;
    const int rsub = tx >> 4;
    const int sg   = tx & 15;
    const int rl0  = 4 * g + 2 * rsub;
    const int rh0  = 76 - 4 * g + 2 * rsub;
    const int jAq  = g + 1;                    // quads with all 4 lane-rows
    const int jBq  = 20 - g;                   // end (exclusive) of high-row quads

    const float nc0 = ncsh[rl0], nc1 = ncsh[rl0 + 1];
    const float nc2 = ncsh[rh0], nc3 = ncsh[rh0 + 1];
    const float cterm = __ldg(g_logdet + bk) + 0.5f * (float)NDIM * LOG_2PI;

    for (int t = 0; t < NT; ++t) {
        float* dcur = (t & 1) ? ds1 : ds0;
        float* dnxt = (t & 1) ? ds0 : ds1;
        const int s0t = cs0 + TS * t;
        int navail = SEQ - s0t; if (navail > TS) navail = TS;

        // Prefetch tile t+1 into the other buffer (overlapped with mainloop)
        if (t + 1 < NT) {
            const int s0n = s0t + TS;
            int navn = SEQ - s0n; if (navn > TS) navn = TS;
            const float* xn = x + ((size_t)b * SEQ + s0n) * NDIM;
            #pragma unroll
            for (int u = 0; u < 4; ++u) {
                int q = tid + u * 320;
                int s = q / 20, j4 = q % 20;
                int nbytes = (s < navn) ? 16 : 0;
                const float* src = (s < navn) ? (xn + s * NDIM + 4 * j4) : xn;
                cpa16(dnxt + s * DSP + 4 * j4, src, nbytes);
            }
        }
        cpa_commit();

        // ---- Mainloop: j-paired accumulation ----
        ull acc[4][4];
        #pragma unroll
        for (int r = 0; r < 4; ++r)
            #pragma unroll
            for (int s = 0; s < 4; ++s) acc[r][s] = 0ULL;

        const float* mp = msh + rl0 * MSP;     // row rl0 (rl0+1 at +MSP)
        const float* hp = msh + rh0 * MSP;     // row rh0 (rh0+1 at +MSP)
        const float* dp = dcur + sg * DSP;     // sample sg (others at +16/32/48*DSP)

        #pragma unroll 2
        for (int jq = 0; jq < jAq; ++jq) {
            ulonglong2 ml0 = *reinterpret_cast<const ulonglong2*>(mp);
            ulonglong2 ml1 = *reinterpret_cast<const ulonglong2*>(mp + MSP);
            ulonglong2 mh0 = *reinterpret_cast<const ulonglong2*>(hp);
            ulonglong2 mh1 = *reinterpret_cast<const ulonglong2*>(hp + MSP);
            ulonglong2 dA = *reinterpret_cast<const ulonglong2*>(dp);
            ulonglong2 dB = *reinterpret_cast<const ulonglong2*>(dp + 16 * DSP);
            ulonglong2 dC = *reinterpret_cast<const ulonglong2*>(dp + 32 * DSP);
            ulonglong2 dD = *reinterpret_cast<const ulonglong2*>(dp + 48 * DSP);
            acc[0][0]=fma2(ml0.x,dA.x,acc[0][0]); acc[0][0]=fma2(ml0.y,dA.y,acc[0][0]);
            acc[0][1]=fma2(ml0.x,dB.x,acc[0][1]); acc[0][1]=fma2(ml0.y,dB.y,acc[0][1]);
            acc[0][2]=fma2(ml0.x,dC.x,acc[0][2]); acc[0][2]=fma2(ml0.y,dC.y,acc[0][2]);
            acc[0][3]=fma2(ml0.x,dD.x,acc[0][3]); acc[0][3]=fma2(ml0.y,dD.y,acc[0][3]);
            acc[1][0]=fma2(ml1.x,dA.x,acc[1][0]); acc[1][0]=fma2(ml1.y,dA.y,acc[1][0]);
            acc[1][1]=fma2(ml1.x,dB.x,acc[1][1]); acc[1][1]=fma2(ml1.y,dB.y,acc[1][1]);
            acc[1][2]=fma2(ml1.x,dC.x,acc[1][2]); acc[1][2]=fma2(ml1.y,dC.y,acc[1][2]);
            acc[1][3]=fma2(ml1.x,dD.x,acc[1][3]); acc[1][3]=fma2(ml1.y,dD.y,acc[1][3]);
            acc[2][0]=fma2(mh0.x,dA.x,acc[2][0]); acc[2][0]=fma2(mh0.y,dA.y,acc[2][0]);
            acc[2][1]=fma2(mh0.x,dB.x,acc[2][1]); acc[2][1]=fma2(mh0.y,dB.y,acc[2][1]);
            acc[2][2]=fma2(mh0.x,dC.x,acc[2][2]); acc[2][2]=fma2(mh0.y,dC.y,acc[2][2]);
            acc[2][3]=fma2(mh0.x,dD.x,acc[2][3]); acc[2][3]=fma2(mh0.y,dD.y,acc[2][3]);
            acc[3][0]=fma2(mh1.x,dA.x,acc[3][0]); acc[3][0]=fma2(mh1.y,dA.y,acc[3][0]);
            acc[3][1]=fma2(mh1.x,dB.x,acc[3][1]); acc[3][1]=fma2(mh1.y,dB.y,acc[3][1]);
            acc[3][2]=fma2(mh1.x,dC.x,acc[3][2]); acc[3][2]=fma2(mh1.y,dC.y,acc[3][2]);
            acc[3][3]=fma2(mh1.x,dD.x,acc[3][3]); acc[3][3]=fma2(mh1.y,dD.y,acc[3][3]);
            mp += 4; hp += 4; dp += 4;
        }
        #pragma unroll 2
        for (int jq = jAq; jq < jBq; ++jq) {
            ulonglong2 mh0 = *reinterpret_cast<const ulonglong2*>(hp);
            ulonglong2 mh1 = *reinterpret_cast<const ulonglong2*>(hp + MSP);
            ulonglong2 dA = *reinterpret_cast<const ulonglong2*>(dp);
            ulonglong2 dB = *reinterpret_cast<const ulonglong2*>(dp + 16 * DSP);
            ulonglong2 dC = *reinterpret_cast<const ulonglong2*>(dp + 32 * DSP);
            ulonglong2 dD = *reinterpret_cast<const ulonglong2*>(dp + 48 * DSP);
            acc[2][0]=fma2(mh0.x,dA.x,acc[2][0]); acc[2][0]=fma2(mh0.y,dA.y,acc[2][0]);
            acc[2][1]=fma2(mh0.x,dB.x,acc[2][1]); acc[2][1]=fma2(mh0.y,dB.y,acc[2][1]);
            acc[2][2]=fma2(mh0.x,dC.x,acc[2][2]); acc[2][2]=fma2(mh0.y,dC.y,acc[2][2]);
            acc[2][3]=fma2(mh0.x,dD.x,acc[2][3]); acc[2][3]=fma2(mh0.y,dD.y,acc[2][3]);
            acc[3][0]=fma2(mh1.x,dA.x,acc[3][0]); acc[3][0]=fma2(mh1.y,dA.y,acc[3][0]);
            acc[3][1]=fma2(mh1.x,dB.x,acc[3][1]); acc[3][1]=fma2(mh1.y,dB.y,acc[3][1]);
            acc[3][2]=fma2(mh1.x,dC.x,acc[3][2]); acc[3][2]=fma2(mh1.y,dC.y,acc[3][2]);
            acc[3][3]=fma2(mh1.x,dD.x,acc[3][3]); acc[3][3]=fma2(mh1.y,dD.y,acc[3][3]);
            hp += 4; dp += 4;
        }

        // ---- Epilogue: z = (hi+lo) - c per row, quad per sample ----
        float qv[4];
        #pragma unroll
        for (int si = 0; si < 4; ++si) {
            float2 f0 = asf2(acc[0][si]);
            float2 f1 = asf2(acc[1][si]);
            float2 f2 = asf2(acc[2][si]);
            float2 f3 = asf2(acc[3][si]);
            float z0 = f0.x + f0.y + nc0;
            float z1 = f1.x + f1.y + nc1;
            float z2 = f2.x + f2.y + nc2;
            float z3 = f3.x + f3.y + nc3;
            float q = z0 * z0 + z1 * z1 + z2 * z2 + z3 * z3;
            q += __shfl_xor_sync(0xffffffffu, q, 16);   // combine rsub pair
            qv[si] = q;
        }
        if (rsub == 0) {
            #pragma unroll
            for (int si = 0; si < 4; ++si)
                red[g * RSP + sg + 16 * si] = qv[si];
        }
        __syncthreads();

        if (tid < navail) {
            float sum = 0.0f;
            #pragma unroll
            for (int gg = 0; gg < 10; ++gg) sum += red[gg * RSP + tid];
            out[((size_t)b * SEQ + s0t + tid) * KST + k] = -0.5f * sum - cterm;
        }

        cpa_wait0();          // next tile's ds ready
        __syncthreads();      // red reads done + buffer swap safe
    }
}

// ---------------------------------------------------------------------------
extern "C" void kernel_launch(void* const* d_in, const int* in_sizes, int n_in,
                              void* d_out, int out_size) {
    const float* x     = (const float*)d_in[0];
    const float* mu    = (const float*)d_in[1];
    const float* sigma = (const float*)d_in[2];
    float* out = (float*)d_out;

    const int llsmem = (NDIM * MSP + 2 * TS * DSP + 10 * RSP + NDIM + 4) * sizeof(float); // ~73 KB
    cudaFuncSetAttribute(ll_kernel, cudaFuncAttributeMaxDynamicSharedMemorySize, llsmem);

    chol_inv_kernel<<<NBK, 96>>>(sigma, mu);

    dim3 grid(SEQ / CHUNK + (SEQ % CHUNK ? 1 : 0), KST, BATCH);   // (2, 12, 64)
    ll_kernel<<<grid, 320, llsmem>>>(x, out);
}